// round 12
// baseline (speedup 1.0000x reference)
#include <cuda_runtime.h>
#include <math.h>

// RoIPool (max) — features (2,256,50,76) f32, rois (128,5) f32 -> out (128,256,7,7) f32
// Bin arithmetic matches the XLA-lowered JAX reference bit-for-bit (x/7 lowered to
// x * fp32(1/7)).
//
// R10 structure (layout transform):
//   K1: NCHW -> NHWC transpose into __device__ scratch (tiled 32x32 smem, both
//       sides coalesced, ~15.6MB L2-resident traffic).
//   K2: warp = (roi, bins, 32-channel group). In NHWC one LDG = one (h,w) cell
//       across 32 channels = exactly 1 cache line. Loop bounds uniform across
//       lanes (no divergence, no predicates); dynamic loops handle ANY bin size
//       (no fallback needed). Output staged in padded smem -> one contiguous
//       coalesced store per block.

#define C_      256
#define H_      50
#define W_      76
#define HWSZ_   (H_ * W_)        // 3800
#define PLANE_  HWSZ_
#define PH_     7
#define PW_     7
#define BINS_   (PH_ * PW_)      // 49
#define NROIS_  128
#define SCALE_  0.0625f
// fp32 nearest to 1/7 (0x3E124925)
#define RECIP7_ 0.14285714924335479736328125f
#define NEG_    (-3.402823466e+38f)

// NHWC scratch: [B][H*W][C]
__device__ float g_feat_t[2 * HWSZ_ * C_];

// ---------------- Kernel 1: NCHW -> NHWC transpose ----------------
// Per batch: transpose (C=256, HW=3800) -> (HW, C). Tile 32(C) x 32(HW).
__global__ __launch_bounds__(256)
void transpose_kernel(const float* __restrict__ feat)
{
    __shared__ float tile[32][33];

    const int b   = blockIdx.z;
    const int hw0 = blockIdx.x * 32;
    const int c0  = blockIdx.y * 32;
    const int tx  = threadIdx.x;       // 0..31
    const int ty  = threadIdx.y;       // 0..7

    const float* src = feat + ((size_t)b * C_) * HWSZ_;

    #pragma unroll
    for (int j = 0; j < 4; ++j) {
        const int c  = c0 + ty + j * 8;
        const int hw = hw0 + tx;
        if (hw < HWSZ_)
            tile[ty + j * 8][tx] = __ldg(src + (size_t)c * HWSZ_ + hw);
    }
    __syncthreads();

    float* dst = g_feat_t + (size_t)b * HWSZ_ * C_;
    #pragma unroll
    for (int j = 0; j < 4; ++j) {
        const int hw = hw0 + ty + j * 8;
        const int c  = c0 + tx;
        if (hw < HWSZ_)
            dst[(size_t)hw * C_ + c] = tile[tx][ty + j * 8];
    }
}

// ---------------- Kernel 2: pooled gather over NHWC ----------------
// block = (roi, cgroup of 32); 8 warps; warp w handles bins {w, w+8, ..., <49}.
#define TPB_  256

__global__ __launch_bounds__(TPB_)
void roipool_kernel(const float* __restrict__ rois,
                    float* __restrict__ out)
{
    const int roi  = blockIdx.x;
    const int c0   = blockIdx.y * 32;
    const int tid  = threadIdx.x;
    const int wid  = tid >> 5;
    const int lane = tid & 31;

    __shared__ int2  s_h[PH_];              // {hstart, hend}
    __shared__ int2  s_w[PW_];              // {wstart, wend}
    __shared__ int   s_b;                   // batch index
    __shared__ float s_out[BINS_ * 33];     // padded staging [bin][33]

    // ---- per-block roi decode (bit-exact XLA arithmetic) ----
    if (tid < 14) {
        const float* r = rois + roi * 5;
        if (tid < PH_) {
            const int y1 = (int)rintf(__fmul_rn(r[2], SCALE_));
            const int y2 = (int)rintf(__fmul_rn(r[4], SCALE_));
            const float bh = __fmul_rn((float)max(y2 - y1 + 1, 1), RECIP7_);
            int hs = (int)floorf(__fmul_rn((float)tid,       bh)) + y1;
            int he = (int)ceilf (__fmul_rn((float)(tid + 1), bh)) + y1;
            s_h[tid] = make_int2(min(max(hs, 0), H_), min(max(he, 0), H_));
            if (tid == 0) s_b = (int)r[0];
        } else {
            const int p  = tid - PH_;
            const int x1 = (int)rintf(__fmul_rn(r[1], SCALE_));
            const int x2 = (int)rintf(__fmul_rn(r[3], SCALE_));
            const float bw = __fmul_rn((float)max(x2 - x1 + 1, 1), RECIP7_);
            int ws = (int)floorf(__fmul_rn((float)p,       bw)) + x1;
            int we = (int)ceilf (__fmul_rn((float)(p + 1), bw)) + x1;
            s_w[p] = make_int2(min(max(ws, 0), W_), min(max(we, 0), W_));
        }
    }
    __syncthreads();

    const float* base = g_feat_t + (size_t)s_b * HWSZ_ * C_ + c0 + lane;

    // ---- pooled gather: every LDG = one (h,w) cell x 32 channels = 1 line ----
    #pragma unroll
    for (int k = 0; k < 7; ++k) {
        const int o = wid + k * 8;
        if (o < BINS_) {
            const int ph = o / PW_;
            const int pw = o - ph * PW_;
            const int2 hb = s_h[ph];
            const int2 wb = s_w[pw];

            float m = NEG_;
            for (int h = hb.x; h < hb.y; ++h) {
                const float* p = base + ((size_t)h * W_ + wb.x) * C_;
                for (int w = wb.x; w < wb.y; ++w, p += C_)
                    m = fmaxf(m, __ldg(p));
            }
            s_out[o * 33 + lane] = (m == NEG_) ? 0.0f : m;   // empty bin -> 0
        }
    }
    __syncthreads();

    // ---- coalesced contiguous write: 32 channels x 49 bins = 1568 floats ----
    float* obase = out + (size_t)roi * (C_ * BINS_) + (size_t)c0 * BINS_;
    for (int idx = tid; idx < 32 * BINS_; idx += TPB_) {
        const int c = idx / BINS_;
        const int s = idx - c * BINS_;
        obase[idx] = s_out[s * 33 + c];
    }
}

extern "C" void kernel_launch(void* const* d_in, const int* in_sizes, int n_in,
                              void* d_out, int out_size)
{
    // Autodetect input order by element count (rois = 640 elems, features = 1,945,600).
    const float* feat;
    const float* rois;
    if (in_sizes[0] == NROIS_ * 5) {
        rois = (const float*)d_in[0];
        feat = (const float*)d_in[1];
    } else {
        feat = (const float*)d_in[0];
        rois = (const float*)d_in[1];
    }
    float* out = (float*)d_out;

    // K1: transpose NCHW -> NHWC
    {
        dim3 block(32, 8);
        dim3 grid((HWSZ_ + 31) / 32, C_ / 32, 2);   // 119 x 8 x 2
        transpose_kernel<<<grid, block>>>(feat);
    }
    // K2: pool
    {
        dim3 block(TPB_);
        dim3 grid(NROIS_, C_ / 32);                 // 128 x 8
        roipool_kernel<<<grid, block>>>(rois, out);
    }
}

// round 14
// speedup vs baseline: 1.2605x; 1.2605x over previous
#include <cuda_runtime.h>
#include <math.h>

// RoIPool (max) — features (2,256,50,76) f32, rois (128,5) f32 -> out (128,256,7,7) f32
// Bin arithmetic matches the XLA-lowered JAX reference bit-for-bit (x/7 lowered to
// x * fp32(1/7)).
//
// R12 structure = R10 layout transform + R5 MLP batching:
//   K1: NCHW -> NHWC transpose into __device__ scratch (tiled 32x32 smem).
//   K2: warp = (roi, 32-channel group, bin subset). NHWC => one LDG = one (h,w)
//       cell x 32 channels = exactly 1 cache line. Per-roi UNIFORM tier dispatch
//       (bin <= 4x4 for this dist) => fully unrolled predicated gather with
//       compile-time immediate offsets -> dozens of independent loads in flight
//       (fixes the MLP=1 serial-chain that made R10 slow). Generic fallback for
//       oversized bins keeps it seed-robust.

#define C_      256
#define H_      50
#define W_      76
#define HWSZ_   (H_ * W_)        // 3800
#define PH_     7
#define PW_     7
#define BINS_   (PH_ * PW_)      // 49
#define NROIS_  128
#define SCALE_  0.0625f
// fp32 nearest to 1/7 (0x3E124925)
#define RECIP7_ 0.14285714924335479736328125f
#define NEG_    (-3.402823466e+38f)

// NHWC scratch: [B][H*W][C]
__device__ float g_feat_t[2 * HWSZ_ * C_];

// ---------------- Kernel 1: NCHW -> NHWC transpose ----------------
__global__ __launch_bounds__(256)
void transpose_kernel(const float* __restrict__ feat)
{
    __shared__ float tile[32][33];

    const int b   = blockIdx.z;
    const int hw0 = blockIdx.x * 32;
    const int c0  = blockIdx.y * 32;
    const int tx  = threadIdx.x;       // 0..31
    const int ty  = threadIdx.y;       // 0..7

    const float* src = feat + ((size_t)b * C_) * HWSZ_;

    #pragma unroll
    for (int j = 0; j < 4; ++j) {
        const int c  = c0 + ty + j * 8;
        const int hw = hw0 + tx;
        if (hw < HWSZ_)
            tile[ty + j * 8][tx] = __ldg(src + (size_t)c * HWSZ_ + hw);
    }
    __syncthreads();

    float* dst = g_feat_t + (size_t)b * HWSZ_ * C_;
    #pragma unroll
    for (int j = 0; j < 4; ++j) {
        const int hw = hw0 + ty + j * 8;
        const int c  = c0 + tx;
        if (hw < HWSZ_)
            dst[(size_t)hw * C_ + c] = tile[tx][ty + j * 8];
    }
}

// ---------------- Kernel 2: pooled gather over NHWC ----------------
#define TPB_  256

template<int NH, int NW>
__device__ __forceinline__ void pool_bins(const float* __restrict__ base,
                                          const int2* __restrict__ s_h,
                                          const int2* __restrict__ s_w,
                                          float* __restrict__ s_out,
                                          int wid, int lane)
{
    #pragma unroll
    for (int k = 0; k < 7; ++k) {
        const int o = wid + k * 8;
        if (o < BINS_) {
            const int ph = o / PW_;
            const int pw = o - ph * PW_;
            const int2 hb = s_h[ph];
            const int2 wb = s_w[pw];
            const int  nh = hb.y - hb.x;
            const int  nw = wb.y - wb.x;
            const float* p0 = base + ((size_t)hb.x * W_ + wb.x) * C_;

            float m = NEG_;
            #pragma unroll
            for (int i = 0; i < NH; ++i) {
                #pragma unroll
                for (int j = 0; j < NW; ++j) {
                    if (i < nh && j < nw)                 // uniform predicates
                        m = fmaxf(m, __ldg(p0 + (i * W_ + j) * C_));  // imm offsets
                }
            }
            s_out[o * 33 + lane] = (m == NEG_) ? 0.0f : m;   // empty bin -> 0
        }
    }
}

__global__ __launch_bounds__(TPB_)
void roipool_kernel(const float* __restrict__ rois,
                    float* __restrict__ out)
{
    const int roi  = blockIdx.x;
    const int c0   = blockIdx.y * 32;
    const int tid  = threadIdx.x;
    const int wid  = tid >> 5;
    const int lane = tid & 31;

    __shared__ int2  s_h[PH_];              // {hstart, hend}
    __shared__ int2  s_w[PW_];              // {wstart, wend}
    __shared__ int   s_b;                   // batch index
    __shared__ int   s_th, s_tw;            // tiers (2/3/4), 0 = fallback
    __shared__ float s_out[BINS_ * 33];     // padded staging [bin][33]

    // ---- per-block roi decode (bit-exact XLA arithmetic) ----
    if (tid < 14) {
        const float* r = rois + roi * 5;
        if (tid < PH_) {
            const int y1 = (int)rintf(__fmul_rn(r[2], SCALE_));
            const int y2 = (int)rintf(__fmul_rn(r[4], SCALE_));
            const float bh = __fmul_rn((float)max(y2 - y1 + 1, 1), RECIP7_);
            int hs = (int)floorf(__fmul_rn((float)tid,       bh)) + y1;
            int he = (int)ceilf (__fmul_rn((float)(tid + 1), bh)) + y1;
            s_h[tid] = make_int2(min(max(hs, 0), H_), min(max(he, 0), H_));
            if (tid == 0) {
                s_b  = (int)r[0];
                s_th = (bh <= 1.0f) ? 2 : (bh <= 2.0f) ? 3 : (bh <= 3.0f) ? 4 : 0;
            }
        } else {
            const int p  = tid - PH_;
            const int x1 = (int)rintf(__fmul_rn(r[1], SCALE_));
            const int x2 = (int)rintf(__fmul_rn(r[3], SCALE_));
            const float bw = __fmul_rn((float)max(x2 - x1 + 1, 1), RECIP7_);
            int ws = (int)floorf(__fmul_rn((float)p,       bw)) + x1;
            int we = (int)ceilf (__fmul_rn((float)(p + 1), bw)) + x1;
            s_w[p] = make_int2(min(max(ws, 0), W_), min(max(we, 0), W_));
            if (p == 0)
                s_tw = (bw <= 1.0f) ? 2 : (bw <= 2.0f) ? 3 : (bw <= 3.0f) ? 4 : 0;
        }
    }
    __syncthreads();

    const float* base = g_feat_t + (size_t)s_b * HWSZ_ * C_ + c0 + lane;
    const int th = s_th, tw = s_tw;         // uniform per block

    if (th && tw) {
        if (th == 2) {
            if      (tw == 2) pool_bins<2,2>(base, s_h, s_w, s_out, wid, lane);
            else if (tw == 3) pool_bins<2,3>(base, s_h, s_w, s_out, wid, lane);
            else              pool_bins<2,4>(base, s_h, s_w, s_out, wid, lane);
        } else if (th == 3) {
            if      (tw == 2) pool_bins<3,2>(base, s_h, s_w, s_out, wid, lane);
            else if (tw == 3) pool_bins<3,3>(base, s_h, s_w, s_out, wid, lane);
            else              pool_bins<3,4>(base, s_h, s_w, s_out, wid, lane);
        } else {
            if      (tw == 2) pool_bins<4,2>(base, s_h, s_w, s_out, wid, lane);
            else if (tw == 3) pool_bins<4,3>(base, s_h, s_w, s_out, wid, lane);
            else              pool_bins<4,4>(base, s_h, s_w, s_out, wid, lane);
        }
    } else {
        // Seed-robust generic fallback (bin_sz > 3 not expected with this dist).
        for (int k = 0; k < 7; ++k) {
            const int o = wid + k * 8;
            if (o < BINS_) {
                const int ph = o / PW_;
                const int pw = o - ph * PW_;
                const int2 hb = s_h[ph];
                const int2 wb = s_w[pw];
                float m = NEG_;
                for (int h = hb.x; h < hb.y; ++h) {
                    const float* p = base + ((size_t)h * W_ + wb.x) * C_;
                    for (int w = wb.x; w < wb.y; ++w, p += C_)
                        m = fmaxf(m, __ldg(p));
                }
                s_out[o * 33 + lane] = (m == NEG_) ? 0.0f : m;
            }
        }
    }
    __syncthreads();

    // ---- coalesced contiguous write: 32 channels x 49 bins = 1568 floats ----
    float* obase = out + (size_t)roi * (C_ * BINS_) + (size_t)c0 * BINS_;
    for (int idx = tid; idx < 32 * BINS_; idx += TPB_) {
        const int c = idx / BINS_;
        const int s = idx - c * BINS_;
        obase[idx] = s_out[s * 33 + c];
    }
}

extern "C" void kernel_launch(void* const* d_in, const int* in_sizes, int n_in,
                              void* d_out, int out_size)
{
    // Autodetect input order by element count (rois = 640 elems, features = 1,945,600).
    const float* feat;
    const float* rois;
    if (in_sizes[0] == NROIS_ * 5) {
        rois = (const float*)d_in[0];
        feat = (const float*)d_in[1];
    } else {
        feat = (const float*)d_in[0];
        rois = (const float*)d_in[1];
    }
    float* out = (float*)d_out;

    // K1: transpose NCHW -> NHWC
    {
        dim3 block(32, 8);
        dim3 grid((HWSZ_ + 31) / 32, C_ / 32, 2);   // 119 x 8 x 2
        transpose_kernel<<<grid, block>>>(feat);
    }
    // K2: pool
    {
        dim3 block(TPB_);
        dim3 grid(NROIS_, C_ / 32);                 // 128 x 8
        roipool_kernel<<<grid, block>>>(rois, out);
    }
}

// round 16
// speedup vs baseline: 1.2849x; 1.0194x over previous
#include <cuda_runtime.h>
#include <math.h>

// RoIPool (max) — features (2,256,50,76) f32, rois (128,5) f32 -> out (128,256,7,7) f32
// Bin arithmetic matches the XLA-lowered JAX reference bit-for-bit (x/7 lowered to
// x * fp32(1/7)).
//
// R14 structure = R12 (NHWC transpose + tier-unrolled pooled gather) with K2
// concurrency fixes:
//   - 512-thread blocks (16 warps): warp w covers bins {w, w+16, w+32, w+48} ->
//     <=4 serial latency waits per warp (was 7)
//   - 16K warps total, 64 warps/SM -> latency hidden by occupancy
//   - NHWC: one LDG = one (h,w) cell x 32 channels = exactly 1 cache line
//   - smem-staged output slab -> one contiguous coalesced store per block

#define C_      256
#define H_      50
#define W_      76
#define HWSZ_   (H_ * W_)        // 3800
#define PH_     7
#define PW_     7
#define BINS_   (PH_ * PW_)      // 49
#define NROIS_  128
#define SCALE_  0.0625f
// fp32 nearest to 1/7 (0x3E124925)
#define RECIP7_ 0.14285714924335479736328125f
#define NEG_    (-3.402823466e+38f)

// NHWC scratch: [B][H*W][C]
__device__ float g_feat_t[2 * HWSZ_ * C_];

// ---------------- Kernel 1: NCHW -> NHWC transpose ----------------
__global__ __launch_bounds__(256)
void transpose_kernel(const float* __restrict__ feat)
{
    __shared__ float tile[32][33];

    const int b   = blockIdx.z;
    const int hw0 = blockIdx.x * 32;
    const int c0  = blockIdx.y * 32;
    const int tx  = threadIdx.x;       // 0..31
    const int ty  = threadIdx.y;       // 0..7

    const float* src = feat + ((size_t)b * C_) * HWSZ_;

    #pragma unroll
    for (int j = 0; j < 4; ++j) {
        const int c  = c0 + ty + j * 8;
        const int hw = hw0 + tx;
        if (hw < HWSZ_)
            tile[ty + j * 8][tx] = __ldg(src + (size_t)c * HWSZ_ + hw);
    }
    __syncthreads();

    float* dst = g_feat_t + (size_t)b * HWSZ_ * C_;
    #pragma unroll
    for (int j = 0; j < 4; ++j) {
        const int hw = hw0 + ty + j * 8;
        const int c  = c0 + tx;
        if (hw < HWSZ_)
            dst[(size_t)hw * C_ + c] = tile[tx][ty + j * 8];
    }
}

// ---------------- Kernel 2: pooled gather over NHWC ----------------
#define TPB_   512              // 16 warps
#define NWRP_  (TPB_ / 32)

template<int NH, int NW>
__device__ __forceinline__ void pool_bins(const float* __restrict__ base,
                                          const int2* __restrict__ s_h,
                                          const int2* __restrict__ s_w,
                                          float* __restrict__ s_out,
                                          int wid, int lane)
{
    #pragma unroll
    for (int k = 0; k < 4; ++k) {
        const int o = wid + k * NWRP_;
        if (o < BINS_) {
            const int ph = o / PW_;
            const int pw = o - ph * PW_;
            const int2 hb = s_h[ph];
            const int2 wb = s_w[pw];
            const int  nh = hb.y - hb.x;
            const int  nw = wb.y - wb.x;
            const float* p0 = base + ((size_t)hb.x * W_ + wb.x) * C_;

            float m = NEG_;
            #pragma unroll
            for (int i = 0; i < NH; ++i) {
                #pragma unroll
                for (int j = 0; j < NW; ++j) {
                    if (i < nh && j < nw)                 // uniform predicates
                        m = fmaxf(m, __ldg(p0 + (i * W_ + j) * C_));  // imm offsets
                }
            }
            s_out[o * 33 + lane] = (m == NEG_) ? 0.0f : m;   // empty bin -> 0
        }
    }
}

__global__ __launch_bounds__(TPB_)
void roipool_kernel(const float* __restrict__ rois,
                    float* __restrict__ out)
{
    const int roi  = blockIdx.x;
    const int c0   = blockIdx.y * 32;
    const int tid  = threadIdx.x;
    const int wid  = tid >> 5;
    const int lane = tid & 31;

    __shared__ int2  s_h[PH_];              // {hstart, hend}
    __shared__ int2  s_w[PW_];              // {wstart, wend}
    __shared__ int   s_b;                   // batch index
    __shared__ int   s_th, s_tw;            // tiers (2/3/4), 0 = fallback
    __shared__ float s_out[BINS_ * 33];     // padded staging [bin][33]

    // ---- per-block roi decode (bit-exact XLA arithmetic) ----
    if (tid < 14) {
        const float* r = rois + roi * 5;
        if (tid < PH_) {
            const int y1 = (int)rintf(__fmul_rn(r[2], SCALE_));
            const int y2 = (int)rintf(__fmul_rn(r[4], SCALE_));
            const float bh = __fmul_rn((float)max(y2 - y1 + 1, 1), RECIP7_);
            int hs = (int)floorf(__fmul_rn((float)tid,       bh)) + y1;
            int he = (int)ceilf (__fmul_rn((float)(tid + 1), bh)) + y1;
            s_h[tid] = make_int2(min(max(hs, 0), H_), min(max(he, 0), H_));
            if (tid == 0) {
                s_b  = (int)r[0];
                s_th = (bh <= 1.0f) ? 2 : (bh <= 2.0f) ? 3 : (bh <= 3.0f) ? 4 : 0;
            }
        } else {
            const int p  = tid - PH_;
            const int x1 = (int)rintf(__fmul_rn(r[1], SCALE_));
            const int x2 = (int)rintf(__fmul_rn(r[3], SCALE_));
            const float bw = __fmul_rn((float)max(x2 - x1 + 1, 1), RECIP7_);
            int ws = (int)floorf(__fmul_rn((float)p,       bw)) + x1;
            int we = (int)ceilf (__fmul_rn((float)(p + 1), bw)) + x1;
            s_w[p] = make_int2(min(max(ws, 0), W_), min(max(we, 0), W_));
            if (p == 0)
                s_tw = (bw <= 1.0f) ? 2 : (bw <= 2.0f) ? 3 : (bw <= 3.0f) ? 4 : 0;
        }
    }
    __syncthreads();

    const float* base = g_feat_t + (size_t)s_b * HWSZ_ * C_ + c0 + lane;
    const int th = s_th, tw = s_tw;         // uniform per block

    if (th && tw) {
        if (th == 2) {
            if      (tw == 2) pool_bins<2,2>(base, s_h, s_w, s_out, wid, lane);
            else if (tw == 3) pool_bins<2,3>(base, s_h, s_w, s_out, wid, lane);
            else              pool_bins<2,4>(base, s_h, s_w, s_out, wid, lane);
        } else if (th == 3) {
            if      (tw == 2) pool_bins<3,2>(base, s_h, s_w, s_out, wid, lane);
            else if (tw == 3) pool_bins<3,3>(base, s_h, s_w, s_out, wid, lane);
            else              pool_bins<3,4>(base, s_h, s_w, s_out, wid, lane);
        } else {
            if      (tw == 2) pool_bins<4,2>(base, s_h, s_w, s_out, wid, lane);
            else if (tw == 3) pool_bins<4,3>(base, s_h, s_w, s_out, wid, lane);
            else              pool_bins<4,4>(base, s_h, s_w, s_out, wid, lane);
        }
    } else {
        // Seed-robust generic fallback (bin_sz > 3 not expected with this dist).
        for (int k = 0; k < 4; ++k) {
            const int o = wid + k * NWRP_;
            if (o < BINS_) {
                const int ph = o / PW_;
                const int pw = o - ph * PW_;
                const int2 hb = s_h[ph];
                const int2 wb = s_w[pw];
                float m = NEG_;
                for (int h = hb.x; h < hb.y; ++h) {
                    const float* p = base + ((size_t)h * W_ + wb.x) * C_;
                    for (int w = wb.x; w < wb.y; ++w, p += C_)
                        m = fmaxf(m, __ldg(p));
                }
                s_out[o * 33 + lane] = (m == NEG_) ? 0.0f : m;
            }
        }
    }
    __syncthreads();

    // ---- coalesced contiguous write: 32 channels x 49 bins = 1568 floats ----
    float* obase = out + (size_t)roi * (C_ * BINS_) + (size_t)c0 * BINS_;
    for (int idx = tid; idx < 32 * BINS_; idx += TPB_) {
        const int c = idx / BINS_;
        const int s = idx - c * BINS_;
        obase[idx] = s_out[s * 33 + c];
    }
}

extern "C" void kernel_launch(void* const* d_in, const int* in_sizes, int n_in,
                              void* d_out, int out_size)
{
    // Autodetect input order by element count (rois = 640 elems, features = 1,945,600).
    const float* feat;
    const float* rois;
    if (in_sizes[0] == NROIS_ * 5) {
        rois = (const float*)d_in[0];
        feat = (const float*)d_in[1];
    } else {
        feat = (const float*)d_in[0];
        rois = (const float*)d_in[1];
    }
    float* out = (float*)d_out;

    // K1: transpose NCHW -> NHWC
    {
        dim3 block(32, 8);
        dim3 grid((HWSZ_ + 31) / 32, C_ / 32, 2);   // 119 x 8 x 2
        transpose_kernel<<<grid, block>>>(feat);
    }
    // K2: pool
    {
        dim3 block(TPB_);
        dim3 grid(NROIS_, C_ / 32);                 // 128 x 8
        roipool_kernel<<<grid, block>>>(rois, out);
    }
}